// round 13
// baseline (speedup 1.0000x reference)
#include <cuda_runtime.h>
#include <cuda_bf16.h>
#include <cstdint>
#include <math_constants.h>

// Problem constants
#define NN 50000
#define EE 800000
#define FF 128
#define HH 8
#define DD 16
// logits = (clip(a,-5,5) + bias) / SCALING, SCALING = D^-0.5 = 0.25  => *4
// |logit| <= (5 + ~6)*4 ~ 44  =>  exp() safely within fp32 range, so the
// segmented softmax is computed WITHOUT max subtraction (bounded inputs).

// ---------------- device scratch (static, no runtime alloc) ----------------
__device__ float g_q[(size_t)NN * FF];
__device__ float g_k[(size_t)NN * FF];
__device__ float g_v[(size_t)NN * FF];
__device__ float g_ex [(size_t)EE * HH];   // CSR-ordered exp(logit)
__device__ float g_exg[(size_t)EE * HH];   // CSR-ordered exp(logit)*gate
__device__ float g_agg[(size_t)NN * FF];
__device__ int   g_cnt[NN];
__device__ int   g_off[NN + 1];
__device__ int   g_cur[NN];
__device__ int   g_pos[EE];       // e -> CSR slot
__device__ int   g_srcperm[EE];   // CSR slot -> src node

// ---------------- CSR build ----------------
__global__ void zero_cnt_kernel() {
    int i = blockIdx.x * blockDim.x + threadIdx.x;
    if (i < NN) g_cnt[i] = 0;
}

__global__ void hist_kernel(const int* __restrict__ dst) {
    int e = blockIdx.x * blockDim.x + threadIdx.x;
    if (e < EE) atomicAdd(&g_cnt[dst[e]], 1);
}

// single-block exclusive scan of g_cnt -> g_off (and g_cur copy)
__global__ void scan_kernel() {
    const int T = 1024;
    __shared__ int sh[T];
    int tid = threadIdx.x;
    const int per = (NN + T - 1) / T;   // 49
    int beg = tid * per;
    int end = beg + per; if (end > NN) end = NN;
    int s = 0;
    for (int i = beg; i < end; i++) s += g_cnt[i];
    sh[tid] = s;
    __syncthreads();
    for (int off = 1; off < T; off <<= 1) {
        int v = (tid >= off) ? sh[tid - off] : 0;
        __syncthreads();
        sh[tid] += v;
        __syncthreads();
    }
    int run = sh[tid] - s;   // exclusive prefix
    for (int i = beg; i < end; i++) {
        g_off[i] = run;
        g_cur[i] = run;
        run += g_cnt[i];
    }
    if (tid == T - 1) g_off[NN] = run;
}

__global__ void fill_kernel(const int* __restrict__ dst,
                            const int* __restrict__ src) {
    int e = blockIdx.x * blockDim.x + threadIdx.x;
    if (e < EE) {
        int p = atomicAdd(&g_cur[dst[e]], 1);
        g_pos[e] = p;
        g_srcperm[p] = src[e];
    }
}

// ---------------- GEMM: C[M,128] = A[M,128] @ W^T (double-buffered) --------
__device__ __forceinline__ void gemm_body(const float* __restrict__ A,
                                          const float* __restrict__ W,
                                          float* __restrict__ C,
                                          int M, int block_m) {
    __shared__ float As[2][8][128];   // As[buf][k][m]
    __shared__ float Bs[2][8][128];   // Bs[buf][k][n]
    const int tid = threadIdx.x;
    const int trow = tid / 16;
    const int tcol = tid % 16;
    const int lr  = tid >> 1;          // 0..127
    const int lc4 = (tid & 1) * 4;     // 0 or 4
    const bool a_valid = (block_m + lr) < M;

    float acc[8][8];
#pragma unroll
    for (int i = 0; i < 8; i++)
#pragma unroll
        for (int j = 0; j < 8; j++) acc[i][j] = 0.0f;

    // preload k0 = 0 into buffer 0
    {
        float4 a4 = make_float4(0.f, 0.f, 0.f, 0.f);
        if (a_valid)
            a4 = *(const float4*)&A[(size_t)(block_m + lr) * 128 + lc4];
        float4 b4 = *(const float4*)&W[(size_t)lr * 128 + lc4];
        As[0][lc4 + 0][lr] = a4.x; As[0][lc4 + 1][lr] = a4.y;
        As[0][lc4 + 2][lr] = a4.z; As[0][lc4 + 3][lr] = a4.w;
        Bs[0][lc4 + 0][lr] = b4.x; Bs[0][lc4 + 1][lr] = b4.y;
        Bs[0][lc4 + 2][lr] = b4.z; Bs[0][lc4 + 3][lr] = b4.w;
    }
    __syncthreads();

    int buf = 0;
    for (int k0 = 0; k0 < 128; k0 += 8) {
        // prefetch next tile into registers (overlaps with compute below)
        float4 na4 = make_float4(0.f, 0.f, 0.f, 0.f);
        float4 nb4 = make_float4(0.f, 0.f, 0.f, 0.f);
        const bool more = (k0 + 8) < 128;
        if (more) {
            if (a_valid)
                na4 = *(const float4*)&A[(size_t)(block_m + lr) * 128 + k0 + 8 + lc4];
            nb4 = *(const float4*)&W[(size_t)lr * 128 + k0 + 8 + lc4];
        }
#pragma unroll
        for (int k = 0; k < 8; k++) {
            float af[8], bf[8];
            *(float4*)&af[0] = *(const float4*)&As[buf][k][trow * 8 + 0];
            *(float4*)&af[4] = *(const float4*)&As[buf][k][trow * 8 + 4];
            *(float4*)&bf[0] = *(const float4*)&Bs[buf][k][tcol * 8 + 0];
            *(float4*)&bf[4] = *(const float4*)&Bs[buf][k][tcol * 8 + 4];
#pragma unroll
            for (int i = 0; i < 8; i++)
#pragma unroll
                for (int j = 0; j < 8; j++) acc[i][j] += af[i] * bf[j];
        }
        if (more) {
            int nb = buf ^ 1;
            As[nb][lc4 + 0][lr] = na4.x; As[nb][lc4 + 1][lr] = na4.y;
            As[nb][lc4 + 2][lr] = na4.z; As[nb][lc4 + 3][lr] = na4.w;
            Bs[nb][lc4 + 0][lr] = nb4.x; Bs[nb][lc4 + 1][lr] = nb4.y;
            Bs[nb][lc4 + 2][lr] = nb4.z; Bs[nb][lc4 + 3][lr] = nb4.w;
            __syncthreads();
            buf = nb;
        }
    }
#pragma unroll
    for (int i = 0; i < 8; i++) {
        int m = block_m + trow * 8 + i;
        if (m < M) {
            *(float4*)&C[(size_t)m * 128 + tcol * 8 + 0] =
                make_float4(acc[i][0], acc[i][1], acc[i][2], acc[i][3]);
            *(float4*)&C[(size_t)m * 128 + tcol * 8 + 4] =
                make_float4(acc[i][4], acc[i][5], acc[i][6], acc[i][7]);
        }
    }
}

// Q, K, V in one grid: blockIdx.y selects which projection.
__global__ void __launch_bounds__(256, 2)
gemm_qkv(const float* __restrict__ A,
         const float* __restrict__ Wq, const float* __restrict__ Wk,
         const float* __restrict__ Wv,
         float* __restrict__ Q, float* __restrict__ K, float* __restrict__ V) {
    const float* W = (blockIdx.y == 0) ? Wq : (blockIdx.y == 1) ? Wk : Wv;
    float*       C = (blockIdx.y == 0) ? Q  : (blockIdx.y == 1) ? K  : V;
    gemm_body(A, W, C, NN, blockIdx.x * 128);
}

__global__ void __launch_bounds__(256, 2)
gemm128_xWt(const float* __restrict__ A, const float* __restrict__ W,
            float* __restrict__ C, int M) {
    gemm_body(A, W, C, M, blockIdx.x * 128);
}

// ---------------- per-edge exp(logit), exp*gate (written CSR-ordered) ------
// 256 threads = 32 edges x 8 heads per block.
__global__ void __launch_bounds__(256)
edge_logits_kernel(const float* __restrict__ ef,
                   const float* __restrict__ Wedge,
                   const float* __restrict__ Wgate,
                   const int* __restrict__ src,
                   const int* __restrict__ dst) {
    __shared__ float We[HH][FF + 4];
    __shared__ float Wg[HH][FF + 4];
    const int tid = threadIdx.x;
    {
        int h = tid >> 5;
        int c = (tid & 31) * 4;
        *(float4*)&We[h][c] = *(const float4*)&Wedge[h * FF + c];
        *(float4*)&Wg[h][c] = *(const float4*)&Wgate[h * FF + c];
    }
    __syncthreads();

    const int e = blockIdx.x * 32 + (tid >> 3);
    const int h = tid & 7;
    const int sn = src[e];
    const int dn = dst[e];
    const int p  = g_pos[e];       // CSR slot (broadcast across 8 head-threads)

    const float4* qrow = (const float4*)&g_q[(size_t)sn * FF + h * DD];
    const float4* krow = (const float4*)&g_k[(size_t)dn * FF + h * DD];
    float a = 0.0f;
#pragma unroll
    for (int j = 0; j < 4; j++) {
        float4 q4 = qrow[j], k4 = krow[j];
        a += q4.x * k4.x + q4.y * k4.y + q4.z * k4.z + q4.w * k4.w;
    }

    const float4* efrow = (const float4*)&ef[(size_t)e * FF];
    float bias = 0.0f, gdot = 0.0f;
#pragma unroll
    for (int k4 = 0; k4 < 32; k4++) {
        float4 e4 = efrow[k4];
        float4 w4 = *(const float4*)&We[h][k4 * 4];
        float4 g4 = *(const float4*)&Wg[h][k4 * 4];
        bias += e4.x * w4.x + e4.y * w4.y + e4.z * w4.z + e4.w * w4.w;
        gdot += e4.x * g4.x + e4.y * g4.y + e4.z * g4.z + e4.w * g4.w;
    }

    float logit = (fminf(fmaxf(a, -5.0f), 5.0f) + bias) * 4.0f;
    float ex    = __expf(logit);                  // bounded; no overflow
    float gate  = 1.0f / (1.0f + __expf(-gdot));
    int idx = p * HH + h;          // CSR-ordered store
    g_ex [idx] = ex;
    g_exg[idx] = ex * gate;
}

// ---------------- node softmax-sum + weighted aggregation (warp per node) --
// ex/exg/srcperm are CSR-contiguous: fully coalesced passes, no exp here.
__global__ void __launch_bounds__(256)
node_agg_kernel() {
    int n = (blockIdx.x * blockDim.x + threadIdx.x) >> 5;
    if (n >= NN) return;
    const int lane = threadIdx.x & 31;
    const int beg = g_off[n];
    const int end = g_off[n + 1];

    // pass A: per-head sum of exp (4 edges in parallel, coalesced 128B/step)
    float hsum = 0.0f;
    for (int i = beg + (lane >> 3); i < end; i += 4) {
        hsum += g_ex[i * HH + (lane & 7)];
    }
    hsum += __shfl_xor_sync(0xFFFFFFFFu, hsum, 8);
    hsum += __shfl_xor_sync(0xFFFFFFFFu, hsum, 16);

    // pass B: weighted aggregation. lane owns head h=lane>>2, cols lane*4..+3
    const int h = lane >> 2;
    float sinv = 1.0f / __shfl_sync(0xFFFFFFFFu, hsum, h);
    float4 acc = make_float4(0.f, 0.f, 0.f, 0.f);
    int i = beg;
    for (; i + 2 <= end; i += 2) {          // unroll x2 for load MLP
        float w0 = g_exg[(i + 0) * HH + h] * sinv;
        float w1 = g_exg[(i + 1) * HH + h] * sinv;
        float4 v0 = *(const float4*)&g_v[(size_t)g_srcperm[i + 0] * FF + lane * 4];
        float4 v1 = *(const float4*)&g_v[(size_t)g_srcperm[i + 1] * FF + lane * 4];
        acc.x += v0.x * w0 + v1.x * w1;
        acc.y += v0.y * w0 + v1.y * w1;
        acc.z += v0.z * w0 + v1.z * w1;
        acc.w += v0.w * w0 + v1.w * w1;
    }
    if (i < end) {
        float w = g_exg[i * HH + h] * sinv;
        float4 v4 = *(const float4*)&g_v[(size_t)g_srcperm[i] * FF + lane * 4];
        acc.x += v4.x * w; acc.y += v4.y * w;
        acc.z += v4.z * w; acc.w += v4.w * w;
    }
    *(float4*)&g_agg[(size_t)n * FF + lane * 4] = acc;
}

// ---------------- host launcher --------------------------------------------
extern "C" void kernel_launch(void* const* d_in, const int* in_sizes, int n_in,
                              void* d_out, int out_size) {
    const float* feat = (const float*)d_in[0];
    const float* ef   = (const float*)d_in[1];
    const float* Wq   = (const float*)d_in[2];
    const float* Wk   = (const float*)d_in[3];
    const float* Wv   = (const float*)d_in[4];
    const float* Wn   = (const float*)d_in[5];
    const float* Wedge= (const float*)d_in[6];
    const float* Wgate= (const float*)d_in[7];
    const int*   src  = (const int*)d_in[8];
    const int*   dst  = (const int*)d_in[9];
    float* out = (float*)d_out;

    void *qp, *kp, *vp, *aggp;
    cudaGetSymbolAddress(&qp, g_q);
    cudaGetSymbolAddress(&kp, g_k);
    cudaGetSymbolAddress(&vp, g_v);
    cudaGetSymbolAddress(&aggp, g_agg);

    // CSR build (cheap int work, runs before the heavy kernels)
    zero_cnt_kernel<<<(NN + 255) / 256, 256>>>();
    hist_kernel<<<(EE + 255) / 256, 256>>>(dst);
    scan_kernel<<<1, 1024>>>();
    fill_kernel<<<(EE + 255) / 256, 256>>>(dst, src);

    const int gm = (NN + 127) / 128;   // 391
    gemm_qkv<<<dim3(gm, 3), 256>>>(feat, Wq, Wk, Wv,
                                   (float*)qp, (float*)kp, (float*)vp);

    edge_logits_kernel<<<EE / 32, 256>>>(ef, Wedge, Wgate, src, dst);
    node_agg_kernel<<<(NN * 32 + 255) / 256, 256>>>();

    gemm128_xWt<<<gm, 256>>>((const float*)aggp, Wn, out, NN);
}

// round 15
// speedup vs baseline: 1.0334x; 1.0334x over previous
#include <cuda_runtime.h>
#include <cuda_bf16.h>
#include <cstdint>
#include <math_constants.h>

// Problem constants
#define NN 50000
#define EE 800000
#define FF 128
#define HH 8
#define DD 16
// logits = (clip(a,-5,5) + bias) / SCALING, SCALING = D^-0.5 = 0.25  => *4
// |logit| <= ~44  =>  exp() safely within fp32 range (max-free softmax).

// ---------------- device scratch (static, no runtime alloc) ----------------
__device__ float g_q[(size_t)NN * FF];
__device__ float g_k[(size_t)NN * FF];
__device__ float g_v[(size_t)NN * FF];
__device__ float g_ex [(size_t)EE * HH];   // CSR-ordered exp(logit)
__device__ float g_exg[(size_t)EE * HH];   // CSR-ordered exp(logit)*gate
__device__ float g_agg[(size_t)NN * FF];
__device__ int   g_cnt[NN];
__device__ int   g_off[NN + 1];
__device__ int   g_cur[NN];
__device__ int   g_pos[EE];       // e -> CSR slot
__device__ int   g_srcperm[EE];   // CSR slot -> src node

// ---------------- packed f32x2 helpers (bit-identical fp32 math) -----------
__device__ __forceinline__ unsigned long long splat_f32x2(float x) {
    unsigned long long r;
    asm("mov.b64 %0, {%1, %1};" : "=l"(r) : "f"(x));
    return r;
}
__device__ __forceinline__ void ffma2(unsigned long long& acc,
                                      unsigned long long a,
                                      unsigned long long b) {
    asm("fma.rn.f32x2 %0, %1, %2, %0;" : "+l"(acc) : "l"(a), "l"(b));
}
__device__ __forceinline__ void unpack2(unsigned long long v, float& lo, float& hi) {
    asm("mov.b64 {%0, %1}, %2;" : "=f"(lo), "=f"(hi) : "l"(v));
}

// ---------------- CSR build ----------------
__global__ void zero_cnt_kernel() {
    int i = blockIdx.x * blockDim.x + threadIdx.x;
    if (i < NN) g_cnt[i] = 0;
}

__global__ void hist_kernel(const int* __restrict__ dst) {
    int e = blockIdx.x * blockDim.x + threadIdx.x;
    if (e < EE) atomicAdd(&g_cnt[dst[e]], 1);
}

// single-block exclusive scan of g_cnt -> g_off (and g_cur copy)
__global__ void scan_kernel() {
    const int T = 1024;
    __shared__ int sh[T];
    int tid = threadIdx.x;
    const int per = (NN + T - 1) / T;   // 49
    int beg = tid * per;
    int end = beg + per; if (end > NN) end = NN;
    int s = 0;
    for (int i = beg; i < end; i++) s += g_cnt[i];
    sh[tid] = s;
    __syncthreads();
    for (int off = 1; off < T; off <<= 1) {
        int v = (tid >= off) ? sh[tid - off] : 0;
        __syncthreads();
        sh[tid] += v;
        __syncthreads();
    }
    int run = sh[tid] - s;   // exclusive prefix
    for (int i = beg; i < end; i++) {
        g_off[i] = run;
        g_cur[i] = run;
        run += g_cnt[i];
    }
    if (tid == T - 1) g_off[NN] = run;
}

__global__ void fill_kernel(const int* __restrict__ dst,
                            const int* __restrict__ src) {
    int e = blockIdx.x * blockDim.x + threadIdx.x;
    if (e < EE) {
        int p = atomicAdd(&g_cur[dst[e]], 1);
        g_pos[e] = p;
        g_srcperm[p] = src[e];
    }
}

// ---------------- GEMM: C[M,128] = A[M,128] @ W^T (f32x2 FFMA2) ------------
// 256 threads, 8x8 per thread; accumulators packed in M-pairs.
__device__ __forceinline__ void gemm_body(const float* __restrict__ A,
                                          const float* __restrict__ W,
                                          float* __restrict__ C,
                                          int M, int block_m) {
    __shared__ float As[2][8][128];   // As[buf][k][m]
    __shared__ float Bs[2][8][128];   // Bs[buf][k][n]
    const int tid = threadIdx.x;
    const int trow = tid / 16;
    const int tcol = tid % 16;
    const int lr  = tid >> 1;          // 0..127
    const int lc4 = (tid & 1) * 4;     // 0 or 4
    const bool a_valid = (block_m + lr) < M;

    // acc2[i2][j] : lo = row trow*8+2*i2, hi = row trow*8+2*i2+1, col tcol*8+j
    unsigned long long acc2[4][8];
#pragma unroll
    for (int i2 = 0; i2 < 4; i2++)
#pragma unroll
        for (int j = 0; j < 8; j++) acc2[i2][j] = 0ULL;

    // preload k0 = 0 into buffer 0
    {
        float4 a4 = make_float4(0.f, 0.f, 0.f, 0.f);
        if (a_valid)
            a4 = *(const float4*)&A[(size_t)(block_m + lr) * 128 + lc4];
        float4 b4 = *(const float4*)&W[(size_t)lr * 128 + lc4];
        As[0][lc4 + 0][lr] = a4.x; As[0][lc4 + 1][lr] = a4.y;
        As[0][lc4 + 2][lr] = a4.z; As[0][lc4 + 3][lr] = a4.w;
        Bs[0][lc4 + 0][lr] = b4.x; Bs[0][lc4 + 1][lr] = b4.y;
        Bs[0][lc4 + 2][lr] = b4.z; Bs[0][lc4 + 3][lr] = b4.w;
    }
    __syncthreads();

    int buf = 0;
    for (int k0 = 0; k0 < 128; k0 += 8) {
        float4 na4 = make_float4(0.f, 0.f, 0.f, 0.f);
        float4 nb4 = make_float4(0.f, 0.f, 0.f, 0.f);
        const bool more = (k0 + 8) < 128;
        if (more) {
            if (a_valid)
                na4 = *(const float4*)&A[(size_t)(block_m + lr) * 128 + k0 + 8 + lc4];
            nb4 = *(const float4*)&W[(size_t)lr * 128 + k0 + 8 + lc4];
        }
#pragma unroll
        for (int k = 0; k < 8; k++) {
            unsigned long long af2[4];
#pragma unroll
            for (int i2 = 0; i2 < 4; i2++)
                af2[i2] = *(const unsigned long long*)&As[buf][k][trow * 8 + i2 * 2];
            float bf[8];
            *(float4*)&bf[0] = *(const float4*)&Bs[buf][k][tcol * 8 + 0];
            *(float4*)&bf[4] = *(const float4*)&Bs[buf][k][tcol * 8 + 4];
#pragma unroll
            for (int j = 0; j < 8; j++) {
                unsigned long long bj = splat_f32x2(bf[j]);
#pragma unroll
                for (int i2 = 0; i2 < 4; i2++)
                    ffma2(acc2[i2][j], af2[i2], bj);
            }
        }
        if (more) {
            int nb = buf ^ 1;
            As[nb][lc4 + 0][lr] = na4.x; As[nb][lc4 + 1][lr] = na4.y;
            As[nb][lc4 + 2][lr] = na4.z; As[nb][lc4 + 3][lr] = na4.w;
            Bs[nb][lc4 + 0][lr] = nb4.x; Bs[nb][lc4 + 1][lr] = nb4.y;
            Bs[nb][lc4 + 2][lr] = nb4.z; Bs[nb][lc4 + 3][lr] = nb4.w;
            __syncthreads();
            buf = nb;
        }
    }

    // epilogue: unpack pairs and store
#pragma unroll
    for (int i2 = 0; i2 < 4; i2++) {
        float lo[8], hi[8];
#pragma unroll
        for (int j = 0; j < 8; j++) unpack2(acc2[i2][j], lo[j], hi[j]);
        int m0 = block_m + trow * 8 + i2 * 2;
        if (m0 < M) {
            *(float4*)&C[(size_t)m0 * 128 + tcol * 8 + 0] =
                make_float4(lo[0], lo[1], lo[2], lo[3]);
            *(float4*)&C[(size_t)m0 * 128 + tcol * 8 + 4] =
                make_float4(lo[4], lo[5], lo[6], lo[7]);
        }
        if (m0 + 1 < M) {
            *(float4*)&C[(size_t)(m0 + 1) * 128 + tcol * 8 + 0] =
                make_float4(hi[0], hi[1], hi[2], hi[3]);
            *(float4*)&C[(size_t)(m0 + 1) * 128 + tcol * 8 + 4] =
                make_float4(hi[4], hi[5], hi[6], hi[7]);
        }
    }
}

// Q, K, V in one grid: blockIdx.y selects which projection.
__global__ void __launch_bounds__(256, 2)
gemm_qkv(const float* __restrict__ A,
         const float* __restrict__ Wq, const float* __restrict__ Wk,
         const float* __restrict__ Wv,
         float* __restrict__ Q, float* __restrict__ K, float* __restrict__ V) {
    const float* W = (blockIdx.y == 0) ? Wq : (blockIdx.y == 1) ? Wk : Wv;
    float*       C = (blockIdx.y == 0) ? Q  : (blockIdx.y == 1) ? K  : V;
    gemm_body(A, W, C, NN, blockIdx.x * 128);
}

__global__ void __launch_bounds__(256, 2)
gemm128_xWt(const float* __restrict__ A, const float* __restrict__ W,
            float* __restrict__ C, int M) {
    gemm_body(A, W, C, M, blockIdx.x * 128);
}

// ---------------- per-edge exp(logit), exp*gate (written CSR-ordered) ------
// 256 threads = 32 edges x 8 heads per block.
__global__ void __launch_bounds__(256)
edge_logits_kernel(const float* __restrict__ ef,
                   const float* __restrict__ Wedge,
                   const float* __restrict__ Wgate,
                   const int* __restrict__ src,
                   const int* __restrict__ dst) {
    __shared__ float We[HH][FF + 4];
    __shared__ float Wg[HH][FF + 4];
    const int tid = threadIdx.x;
    {
        int h = tid >> 5;
        int c = (tid & 31) * 4;
        *(float4*)&We[h][c] = *(const float4*)&Wedge[h * FF + c];
        *(float4*)&Wg[h][c] = *(const float4*)&Wgate[h * FF + c];
    }
    __syncthreads();

    const int e = blockIdx.x * 32 + (tid >> 3);
    const int h = tid & 7;
    const int sn = src[e];
    const int dn = dst[e];
    const int p  = g_pos[e];       // CSR slot (broadcast across 8 head-threads)

    const float4* qrow = (const float4*)&g_q[(size_t)sn * FF + h * DD];
    const float4* krow = (const float4*)&g_k[(size_t)dn * FF + h * DD];
    float a = 0.0f;
#pragma unroll
    for (int j = 0; j < 4; j++) {
        float4 q4 = qrow[j], k4 = krow[j];
        a += q4.x * k4.x + q4.y * k4.y + q4.z * k4.z + q4.w * k4.w;
    }

    const float4* efrow = (const float4*)&ef[(size_t)e * FF];
    float bias = 0.0f, gdot = 0.0f;
#pragma unroll
    for (int k4 = 0; k4 < 32; k4++) {
        float4 e4 = efrow[k4];
        float4 w4 = *(const float4*)&We[h][k4 * 4];
        float4 g4 = *(const float4*)&Wg[h][k4 * 4];
        bias += e4.x * w4.x + e4.y * w4.y + e4.z * w4.z + e4.w * w4.w;
        gdot += e4.x * g4.x + e4.y * g4.y + e4.z * g4.z + e4.w * g4.w;
    }

    float logit = (fminf(fmaxf(a, -5.0f), 5.0f) + bias) * 4.0f;
    float ex    = __expf(logit);                  // bounded; no overflow
    float gate  = 1.0f / (1.0f + __expf(-gdot));
    int idx = p * HH + h;          // CSR-ordered store
    g_ex [idx] = ex;
    g_exg[idx] = ex * gate;
}

// ---------------- node softmax-sum + weighted aggregation (warp per node) --
// ex/exg/srcperm are CSR-contiguous: fully coalesced passes, no exp here.
__global__ void __launch_bounds__(256)
node_agg_kernel() {
    int n = (blockIdx.x * blockDim.x + threadIdx.x) >> 5;
    if (n >= NN) return;
    const int lane = threadIdx.x & 31;
    const int beg = g_off[n];
    const int end = g_off[n + 1];

    // pass A: per-head sum of exp (4 edges in parallel, coalesced 128B/step)
    float hsum = 0.0f;
    for (int i = beg + (lane >> 3); i < end; i += 4) {
        hsum += g_ex[i * HH + (lane & 7)];
    }
    hsum += __shfl_xor_sync(0xFFFFFFFFu, hsum, 8);
    hsum += __shfl_xor_sync(0xFFFFFFFFu, hsum, 16);

    // pass B: weighted aggregation. lane owns head h=lane>>2, cols lane*4..+3
    const int h = lane >> 2;
    float sinv = 1.0f / __shfl_sync(0xFFFFFFFFu, hsum, h);
    float4 acc = make_float4(0.f, 0.f, 0.f, 0.f);
    int i = beg;
    for (; i + 2 <= end; i += 2) {          // unroll x2 for load MLP
        float w0 = g_exg[(i + 0) * HH + h] * sinv;
        float w1 = g_exg[(i + 1) * HH + h] * sinv;
        float4 v0 = *(const float4*)&g_v[(size_t)g_srcperm[i + 0] * FF + lane * 4];
        float4 v1 = *(const float4*)&g_v[(size_t)g_srcperm[i + 1] * FF + lane * 4];
        acc.x += v0.x * w0 + v1.x * w1;
        acc.y += v0.y * w0 + v1.y * w1;
        acc.z += v0.z * w0 + v1.z * w1;
        acc.w += v0.w * w0 + v1.w * w1;
    }
    if (i < end) {
        float w = g_exg[i * HH + h] * sinv;
        float4 v4 = *(const float4*)&g_v[(size_t)g_srcperm[i] * FF + lane * 4];
        acc.x += v4.x * w; acc.y += v4.y * w;
        acc.z += v4.z * w; acc.w += v4.w * w;
    }
    *(float4*)&g_agg[(size_t)n * FF + lane * 4] = acc;
}

// ---------------- host launcher --------------------------------------------
extern "C" void kernel_launch(void* const* d_in, const int* in_sizes, int n_in,
                              void* d_out, int out_size) {
    const float* feat = (const float*)d_in[0];
    const float* ef   = (const float*)d_in[1];
    const float* Wq   = (const float*)d_in[2];
    const float* Wk   = (const float*)d_in[3];
    const float* Wv   = (const float*)d_in[4];
    const float* Wn   = (const float*)d_in[5];
    const float* Wedge= (const float*)d_in[6];
    const float* Wgate= (const float*)d_in[7];
    const int*   src  = (const int*)d_in[8];
    const int*   dst  = (const int*)d_in[9];
    float* out = (float*)d_out;

    void *qp, *kp, *vp, *aggp;
    cudaGetSymbolAddress(&qp, g_q);
    cudaGetSymbolAddress(&kp, g_k);
    cudaGetSymbolAddress(&vp, g_v);
    cudaGetSymbolAddress(&aggp, g_agg);

    // CSR build (cheap int work, runs before the heavy kernels)
    zero_cnt_kernel<<<(NN + 255) / 256, 256>>>();
    hist_kernel<<<(EE + 255) / 256, 256>>>(dst);
    scan_kernel<<<1, 1024>>>();
    fill_kernel<<<(EE + 255) / 256, 256>>>(dst, src);

    const int gm = (NN + 127) / 128;   // 391
    gemm_qkv<<<dim3(gm, 3), 256>>>(feat, Wq, Wk, Wv,
                                   (float*)qp, (float*)kp, (float*)vp);

    edge_logits_kernel<<<EE / 32, 256>>>(ef, Wedge, Wgate, src, dst);
    node_agg_kernel<<<(NN * 32 + 255) / 256, 256>>>();

    gemm128_xWt<<<gm, 256>>>((const float*)aggp, Wn, out, NN);
}